// round 4
// baseline (speedup 1.0000x reference)
#include <cuda_runtime.h>
#include <mma.h>
#include <cstdint>

using namespace nvcuda;

#define NODES_MAX 50000
#define PAD_M     50176      // 392*128, pad for unguarded wmma stores
#define E_MAX     1000000
#define IN_C  256
#define HID_C 128
#define OUT_C 64

// ---------------- scratch ----------------------------------------------------
__device__ float g_f1[PAD_M * HID_C];        // gemm1 raw output (X@W1)
__device__ float g_a1[NODES_MAX * HID_C];    // layer-1 aggregated (pre-bias/relu)
__device__ float g_f2[PAD_M * OUT_C];        // gemm2 raw output
__device__ float g_dinv[NODES_MAX];
__device__ int   g_deg [NODES_MAX];
__device__ int   g_row_start[NODES_MAX + 1];
__device__ int   g_cursor[NODES_MAX];
__device__ int   g_src[E_MAX];               // CSR-by-dst: source node per slot
__device__ int   g_is64;

// ---------------- prep: zero deg + dtype detect ------------------------------
__global__ void prep_kernel(const long long* __restrict__ p, int E, int M) {
    int i = blockIdx.x * blockDim.x + threadIdx.x;
    if (i < M) g_deg[i] = 0;
    if (blockIdx.x == 0) {
        __shared__ int bad;
        if (threadIdx.x == 0) bad = 0;
        __syncthreads();
        if ((int)threadIdx.x < 256 && (int)threadIdx.x < E) {
            long long v = p[threadIdx.x];
            if (v < 0 || v >= (long long)M) bad = 1;
        }
        __syncthreads();
        if (threadIdx.x == 0) g_is64 = bad ? 0 : 1;
    }
}

__device__ __forceinline__ void get_edge(const void* ei, int e, int E, int is64,
                                         int& s, int& d) {
    if (is64) {
        const long long* p = (const long long*)ei;
        s = (int)p[e]; d = (int)p[E + e];
    } else {
        const int* p = (const int*)ei;
        s = p[e]; d = p[E + e];
    }
}

__global__ void count_deg_kernel(const void* __restrict__ ei, int E) {
    int e = blockIdx.x * blockDim.x + threadIdx.x;
    if (e >= E) return;
    int s, d;
    get_edge(ei, e, E, g_is64, s, d);
    atomicAdd(&g_deg[d], 1);
}

__global__ void dinv_kernel(int M) {
    int i = blockIdx.x * blockDim.x + threadIdx.x;
    if (i < M) g_dinv[i] = rsqrtf((float)(g_deg[i] + 1));  // +1 self loop
}

// ---------------- exclusive scan of deg -> row_start, cursor (1 block) ------
__global__ void scan_kernel(int M, int E) {
    __shared__ int ssum[1024];
    int t = threadIdx.x;
    int chunk = (M + 1023) / 1024;
    int lo = t * chunk;
    int hi = min(lo + chunk, M);
    int s = 0;
    for (int i = lo; i < hi; ++i) s += g_deg[i];
    ssum[t] = s;
    __syncthreads();
    for (int off = 1; off < 1024; off <<= 1) {
        int v = (t >= off) ? ssum[t - off] : 0;
        __syncthreads();
        ssum[t] += v;
        __syncthreads();
    }
    int run = (t > 0) ? ssum[t - 1] : 0;   // exclusive base
    for (int i = lo; i < hi; ++i) {
        g_row_start[i] = run;
        g_cursor[i]    = run;
        run += g_deg[i];
    }
    if (t == 1023) g_row_start[M] = E;
}

__global__ void fill_kernel(const void* __restrict__ ei, int E) {
    int e = blockIdx.x * blockDim.x + threadIdx.x;
    if (e >= E) return;
    int s, d;
    get_edge(ei, e, E, g_is64, s, d);
    int pos = atomicAdd(&g_cursor[d], 1);
    g_src[pos] = s;
}

// ---------------- GEMM1 (TF32 wmma): g_f1 = X @ W1 (raw) --------------------
// BM=128 BN=128 BK=32, 8 warps, warp tile 32x64. tf32 cvt hoisted to smem fill.
__global__ __launch_bounds__(256, 2) void gemm1_kernel(
    const float* __restrict__ A, const float* __restrict__ W, int M) {
    __shared__ float As[128][40];
    __shared__ float Bs[32][136];
    int tid = threadIdx.x;
    int wid = tid >> 5;
    int wm = wid & 3;
    int wn = wid >> 2;
    int bm = blockIdx.x * 128;

    wmma::fragment<wmma::accumulator, 16, 16, 8, float> c[2][4];
    #pragma unroll
    for (int i = 0; i < 2; i++)
        #pragma unroll
        for (int j = 0; j < 4; j++) wmma::fill_fragment(c[i][j], 0.f);

    for (int k0 = 0; k0 < IN_C; k0 += 32) {
        #pragma unroll
        for (int i = 0; i < 4; ++i) {
            int idx = tid * 4 + i;
            int r = idx >> 3, c4 = (idx & 7) * 4;
            int gm = bm + r;
            float4 v = make_float4(0.f, 0.f, 0.f, 0.f);
            if (gm < M) v = *(const float4*)&A[(size_t)gm * IN_C + k0 + c4];
            v.x = wmma::__float_to_tf32(v.x); v.y = wmma::__float_to_tf32(v.y);
            v.z = wmma::__float_to_tf32(v.z); v.w = wmma::__float_to_tf32(v.w);
            *(float4*)&As[r][c4] = v;
        }
        #pragma unroll
        for (int i = 0; i < 4; ++i) {
            int idx = tid * 4 + i;
            int kk = idx >> 5, n4 = (idx & 31) * 4;
            float4 v = *(const float4*)&W[(size_t)(k0 + kk) * HID_C + n4];
            v.x = wmma::__float_to_tf32(v.x); v.y = wmma::__float_to_tf32(v.y);
            v.z = wmma::__float_to_tf32(v.z); v.w = wmma::__float_to_tf32(v.w);
            *(float4*)&Bs[kk][n4] = v;
        }
        __syncthreads();
        #pragma unroll
        for (int ks = 0; ks < 32; ks += 8) {
            wmma::fragment<wmma::matrix_a, 16, 16, 8, wmma::precision::tf32, wmma::row_major> a[2];
            wmma::fragment<wmma::matrix_b, 16, 16, 8, wmma::precision::tf32, wmma::row_major> b[4];
            #pragma unroll
            for (int i = 0; i < 2; i++)
                wmma::load_matrix_sync(a[i], &As[wm * 32 + i * 16][ks], 40);
            #pragma unroll
            for (int j = 0; j < 4; j++)
                wmma::load_matrix_sync(b[j], &Bs[ks][wn * 64 + j * 16], 136);
            #pragma unroll
            for (int i = 0; i < 2; i++)
                #pragma unroll
                for (int j = 0; j < 4; j++)
                    wmma::mma_sync(c[i][j], a[i], b[j], c[i][j]);
        }
        __syncthreads();
    }
    #pragma unroll
    for (int i = 0; i < 2; i++)
        #pragma unroll
        for (int j = 0; j < 4; j++) {
            size_t off = (size_t)(bm + wm * 32 + i * 16) * HID_C + wn * 64 + j * 16;
            wmma::store_matrix_sync(&g_f1[off], c[i][j], HID_C, wmma::mem_row_major);
        }
}

// ---------------- gather layer 1: a1[d] = dinv[d]*(Σ f1[s]*dinv[s] + f1[d]*dinv[d])
// warp per node, lane owns float4 (128 floats / 32 lanes).
__global__ __launch_bounds__(256) void gather1_kernel(int M) {
    int w    = (blockIdx.x * blockDim.x + threadIdx.x) >> 5;
    int lane = threadIdx.x & 31;
    if (w >= M) return;
    int start = g_row_start[w];
    int end   = g_row_start[w + 1];
    float dn = g_dinv[w];
    float4 acc = __ldg((const float4*)&g_f1[(size_t)w * HID_C] + lane);
    acc.x *= dn; acc.y *= dn; acc.z *= dn; acc.w *= dn;

    int i = start;
    for (; i + 4 <= end; i += 4) {
        int s0 = g_src[i], s1 = g_src[i + 1], s2 = g_src[i + 2], s3 = g_src[i + 3];
        float d0 = g_dinv[s0], d1 = g_dinv[s1], d2 = g_dinv[s2], d3 = g_dinv[s3];
        float4 v0 = __ldg((const float4*)&g_f1[(size_t)s0 * HID_C] + lane);
        float4 v1 = __ldg((const float4*)&g_f1[(size_t)s1 * HID_C] + lane);
        float4 v2 = __ldg((const float4*)&g_f1[(size_t)s2 * HID_C] + lane);
        float4 v3 = __ldg((const float4*)&g_f1[(size_t)s3 * HID_C] + lane);
        acc.x += v0.x * d0 + v1.x * d1 + v2.x * d2 + v3.x * d3;
        acc.y += v0.y * d0 + v1.y * d1 + v2.y * d2 + v3.y * d3;
        acc.z += v0.z * d0 + v1.z * d1 + v2.z * d2 + v3.z * d3;
        acc.w += v0.w * d0 + v1.w * d1 + v2.w * d2 + v3.w * d3;
    }
    for (; i < end; ++i) {
        int s = g_src[i];
        float ds = g_dinv[s];
        float4 v = __ldg((const float4*)&g_f1[(size_t)s * HID_C] + lane);
        acc.x += v.x * ds; acc.y += v.y * ds; acc.z += v.z * ds; acc.w += v.w * ds;
    }
    acc.x *= dn; acc.y *= dn; acc.z *= dn; acc.w *= dn;
    *((float4*)&g_a1[(size_t)w * HID_C] + lane) = acc;
}

// ---------------- GEMM2 (TF32 wmma): g_f2 = relu(a1 + b1) @ W2 (raw) --------
__global__ __launch_bounds__(256, 2) void gemm2_kernel(
    const float* __restrict__ W, const float* __restrict__ b1, int M) {
    __shared__ float As[128][40];
    __shared__ float Bs[32][72];
    __shared__ float b1s[HID_C];
    int tid = threadIdx.x;
    int wid = tid >> 5;
    int wm = wid & 3;
    int wn = wid >> 2;
    int bm = blockIdx.x * 128;
    if (tid < HID_C / 4) ((float4*)b1s)[tid] = ((const float4*)b1)[tid];
    __syncthreads();

    wmma::fragment<wmma::accumulator, 16, 16, 8, float> c[2][2];
    #pragma unroll
    for (int i = 0; i < 2; i++)
        #pragma unroll
        for (int j = 0; j < 2; j++) wmma::fill_fragment(c[i][j], 0.f);

    for (int k0 = 0; k0 < HID_C; k0 += 32) {
        #pragma unroll
        for (int i = 0; i < 4; ++i) {
            int idx = tid * 4 + i;
            int r = idx >> 3, c4 = (idx & 7) * 4;
            int gm = bm + r;
            float4 v = make_float4(0.f, 0.f, 0.f, 0.f);
            if (gm < M) {
                v = *(const float4*)&g_a1[(size_t)gm * HID_C + k0 + c4];
                v.x = fmaxf(v.x + b1s[k0 + c4 + 0], 0.f);
                v.y = fmaxf(v.y + b1s[k0 + c4 + 1], 0.f);
                v.z = fmaxf(v.z + b1s[k0 + c4 + 2], 0.f);
                v.w = fmaxf(v.w + b1s[k0 + c4 + 3], 0.f);
                v.x = wmma::__float_to_tf32(v.x); v.y = wmma::__float_to_tf32(v.y);
                v.z = wmma::__float_to_tf32(v.z); v.w = wmma::__float_to_tf32(v.w);
            }
            *(float4*)&As[r][c4] = v;
        }
        #pragma unroll
        for (int i = 0; i < 2; ++i) {
            int idx = tid * 2 + i;
            int kk = idx >> 4, n4 = (idx & 15) * 4;
            float4 v = *(const float4*)&W[(size_t)(k0 + kk) * OUT_C + n4];
            v.x = wmma::__float_to_tf32(v.x); v.y = wmma::__float_to_tf32(v.y);
            v.z = wmma::__float_to_tf32(v.z); v.w = wmma::__float_to_tf32(v.w);
            *(float4*)&Bs[kk][n4] = v;
        }
        __syncthreads();
        #pragma unroll
        for (int ks = 0; ks < 32; ks += 8) {
            wmma::fragment<wmma::matrix_a, 16, 16, 8, wmma::precision::tf32, wmma::row_major> a[2];
            wmma::fragment<wmma::matrix_b, 16, 16, 8, wmma::precision::tf32, wmma::row_major> b[2];
            #pragma unroll
            for (int i = 0; i < 2; i++)
                wmma::load_matrix_sync(a[i], &As[wm * 32 + i * 16][ks], 40);
            #pragma unroll
            for (int j = 0; j < 2; j++)
                wmma::load_matrix_sync(b[j], &Bs[ks][wn * 32 + j * 16], 72);
            #pragma unroll
            for (int i = 0; i < 2; i++)
                #pragma unroll
                for (int j = 0; j < 2; j++)
                    wmma::mma_sync(c[i][j], a[i], b[j], c[i][j]);
        }
        __syncthreads();
    }
    #pragma unroll
    for (int i = 0; i < 2; i++)
        #pragma unroll
        for (int j = 0; j < 2; j++) {
            size_t off = (size_t)(bm + wm * 32 + i * 16) * OUT_C + wn * 32 + j * 16;
            wmma::store_matrix_sync(&g_f2[off], c[i][j], OUT_C, wmma::mem_row_major);
        }
}

// ---------------- gather layer 2 + bias: out[d] = dinv[d]*(Σ f2[s]*dinv[s]
//                  + f2[d]*dinv[d]) + b2.  Half-warp (16 lanes) per node.
__global__ __launch_bounds__(256) void gather2_kernel(
    float* __restrict__ out, const float* __restrict__ b2, int M) {
    int t    = blockIdx.x * blockDim.x + threadIdx.x;
    int n    = t >> 4;
    int lane = t & 15;
    if (n >= M) return;
    int start = g_row_start[n];
    int end   = g_row_start[n + 1];
    float dn = g_dinv[n];
    float4 acc = __ldg((const float4*)&g_f2[(size_t)n * OUT_C] + lane);
    acc.x *= dn; acc.y *= dn; acc.z *= dn; acc.w *= dn;

    int i = start;
    for (; i + 4 <= end; i += 4) {
        int s0 = g_src[i], s1 = g_src[i + 1], s2 = g_src[i + 2], s3 = g_src[i + 3];
        float d0 = g_dinv[s0], d1 = g_dinv[s1], d2 = g_dinv[s2], d3 = g_dinv[s3];
        float4 v0 = __ldg((const float4*)&g_f2[(size_t)s0 * OUT_C] + lane);
        float4 v1 = __ldg((const float4*)&g_f2[(size_t)s1 * OUT_C] + lane);
        float4 v2 = __ldg((const float4*)&g_f2[(size_t)s2 * OUT_C] + lane);
        float4 v3 = __ldg((const float4*)&g_f2[(size_t)s3 * OUT_C] + lane);
        acc.x += v0.x * d0 + v1.x * d1 + v2.x * d2 + v3.x * d3;
        acc.y += v0.y * d0 + v1.y * d1 + v2.y * d2 + v3.y * d3;
        acc.z += v0.z * d0 + v1.z * d1 + v2.z * d2 + v3.z * d3;
        acc.w += v0.w * d0 + v1.w * d1 + v2.w * d2 + v3.w * d3;
    }
    for (; i < end; ++i) {
        int s = g_src[i];
        float ds = g_dinv[s];
        float4 v = __ldg((const float4*)&g_f2[(size_t)s * OUT_C] + lane);
        acc.x += v.x * ds; acc.y += v.y * ds; acc.z += v.z * ds; acc.w += v.w * ds;
    }
    float4 bb = __ldg((const float4*)b2 + lane);
    acc.x = acc.x * dn + bb.x; acc.y = acc.y * dn + bb.y;
    acc.z = acc.z * dn + bb.z; acc.w = acc.w * dn + bb.w;
    *((float4*)&out[(size_t)n * OUT_C] + lane) = acc;
}

// ---------------- launch ----------------------------------------------------
extern "C" void kernel_launch(void* const* d_in, const int* in_sizes, int n_in,
                              void* d_out, int out_size) {
    const float* features = (const float*)d_in[0];
    const void*  edge_idx = d_in[1];
    const float* W1 = (const float*)d_in[2];
    const float* b1 = (const float*)d_in[3];
    const float* W2 = (const float*)d_in[4];
    const float* b2 = (const float*)d_in[5];
    float* out = (float*)d_out;

    int M = in_sizes[0] / IN_C;       // 50000
    int E = in_sizes[1] / 2;          // 800000

    prep_kernel<<<(M + 255) / 256, 256>>>((const long long*)edge_idx, E, M);
    count_deg_kernel<<<(E + 255) / 256, 256>>>(edge_idx, E);
    dinv_kernel<<<(M + 255) / 256, 256>>>(M);
    scan_kernel<<<1, 1024>>>(M, E);
    fill_kernel<<<(E + 255) / 256, 256>>>(edge_idx, E);

    int gblocks = (M + 127) / 128;    // 391
    gemm1_kernel<<<gblocks, 256>>>(features, W1, M);

    long long t1 = (long long)M * 32;
    gather1_kernel<<<(unsigned)((t1 + 255) / 256), 256>>>(M);

    gemm2_kernel<<<gblocks, 256>>>(W2, b1, M);

    long long t2 = (long long)M * 16;
    gather2_kernel<<<(unsigned)((t2 + 255) / 256), 256>>>(out, b2, M);
}

// round 5
// speedup vs baseline: 1.4070x; 1.4070x over previous
#include <cuda_runtime.h>
#include <mma.h>
#include <cstdint>

using namespace nvcuda;

#define NODES_MAX 50000
#define PAD_M     50176      // 392*128, pad for unguarded wmma stores
#define E_MAX     1000000
#define IN_C  256
#define HID_C 128
#define OUT_C 64

#define SCAN_B    196        // scan blocks: 196*256 = 50176 >= NODES_MAX

// ---------------- scratch ----------------------------------------------------
__device__ float g_f1[PAD_M * HID_C];        // gemm1 raw output (X@W1)
__device__ float g_a1[NODES_MAX * HID_C];    // layer-1 aggregated (pre-bias/relu)
__device__ float g_f2[PAD_M * OUT_C];        // gemm2 raw output
__device__ float g_dinv[NODES_MAX];
__device__ int   g_deg [NODES_MAX];
__device__ int   g_row_start[NODES_MAX + 1];
__device__ int   g_cursor[NODES_MAX];
__device__ int   g_src[E_MAX];               // CSR-by-dst: source node per slot
__device__ int   g_bsum[SCAN_B];             // per-block deg sums
__device__ int   g_boff[SCAN_B];             // exclusive scan of g_bsum
__device__ int   g_is64;

// ---------------- prep: zero deg + dtype detect ------------------------------
__global__ void prep_kernel(const long long* __restrict__ p, int E, int M) {
    int i = blockIdx.x * blockDim.x + threadIdx.x;
    if (i < M) g_deg[i] = 0;
    if (blockIdx.x == 0) {
        __shared__ int bad;
        if (threadIdx.x == 0) bad = 0;
        __syncthreads();
        if ((int)threadIdx.x < 256 && (int)threadIdx.x < E) {
            long long v = p[threadIdx.x];
            if (v < 0 || v >= (long long)M) bad = 1;
        }
        __syncthreads();
        if (threadIdx.x == 0) g_is64 = bad ? 0 : 1;
    }
}

__device__ __forceinline__ void get_edge(const void* ei, int e, int E, int is64,
                                         int& s, int& d) {
    if (is64) {
        const long long* p = (const long long*)ei;
        s = (int)p[e]; d = (int)p[E + e];
    } else {
        const int* p = (const int*)ei;
        s = p[e]; d = p[E + e];
    }
}

__global__ void count_deg_kernel(const void* __restrict__ ei, int E) {
    int e = blockIdx.x * blockDim.x + threadIdx.x;
    if (e >= E) return;
    int s, d;
    get_edge(ei, e, E, g_is64, s, d);
    atomicAdd(&g_deg[d], 1);
}

// ---------------- hierarchical scan -----------------------------------------
// scan1: per-block reduce of deg -> g_bsum; also dinv = rsqrt(deg+1)
__global__ __launch_bounds__(256) void scan1_kernel(int M) {
    __shared__ int red[8];
    int i = blockIdx.x * 256 + threadIdx.x;
    int d = (i < M) ? g_deg[i] : 0;
    if (i < M) g_dinv[i] = rsqrtf((float)(d + 1));
    int v = d;
    #pragma unroll
    for (int off = 16; off > 0; off >>= 1) v += __shfl_down_sync(0xffffffffu, v, off);
    if ((threadIdx.x & 31) == 0) red[threadIdx.x >> 5] = v;
    __syncthreads();
    if (threadIdx.x < 8) {
        int s = red[threadIdx.x];
        #pragma unroll
        for (int off = 4; off > 0; off >>= 1) s += __shfl_down_sync(0xffu, s, off);
        if (threadIdx.x == 0) g_bsum[blockIdx.x] = s;
    }
}

// scan2: exclusive scan of SCAN_B block sums (1 block, 256 threads)
__global__ __launch_bounds__(256) void scan2_kernel() {
    __shared__ int sm[256];
    int t = threadIdx.x;
    sm[t] = (t < SCAN_B) ? g_bsum[t] : 0;
    __syncthreads();
    #pragma unroll
    for (int off = 1; off < 256; off <<= 1) {
        int v = (t >= off) ? sm[t - off] : 0;
        __syncthreads();
        sm[t] += v;
        __syncthreads();
    }
    if (t < SCAN_B) g_boff[t] = (t > 0) ? sm[t - 1] : 0;   // exclusive
}

// scan3: block-local exclusive scan + block offset -> row_start, cursor
__global__ __launch_bounds__(256) void scan3_kernel(int M, int E) {
    __shared__ int sm[256];
    int t = threadIdx.x;
    int i = blockIdx.x * 256 + t;
    int d = (i < M) ? g_deg[i] : 0;
    sm[t] = d;
    __syncthreads();
    #pragma unroll
    for (int off = 1; off < 256; off <<= 1) {
        int v = (t >= off) ? sm[t - off] : 0;
        __syncthreads();
        sm[t] += v;
        __syncthreads();
    }
    if (i < M) {
        int rs = g_boff[blockIdx.x] + sm[t] - d;    // exclusive prefix
        g_row_start[i] = rs;
        g_cursor[i]    = rs;
    }
    if (i == M - 1 || (blockIdx.x == 0 && t == 0 && M == 0))
        g_row_start[M] = E;
}

__global__ void fill_kernel(const void* __restrict__ ei, int E) {
    int e = blockIdx.x * blockDim.x + threadIdx.x;
    if (e >= E) return;
    int s, d;
    get_edge(ei, e, E, g_is64, s, d);
    int pos = atomicAdd(&g_cursor[d], 1);
    g_src[pos] = s;
}

// ---------------- GEMM1 (TF32 wmma): g_f1 = X @ W1 (raw) --------------------
__global__ __launch_bounds__(256, 2) void gemm1_kernel(
    const float* __restrict__ A, const float* __restrict__ W, int M) {
    __shared__ float As[128][40];
    __shared__ float Bs[32][136];
    int tid = threadIdx.x;
    int wid = tid >> 5;
    int wm = wid & 3;
    int wn = wid >> 2;
    int bm = blockIdx.x * 128;

    wmma::fragment<wmma::accumulator, 16, 16, 8, float> c[2][4];
    #pragma unroll
    for (int i = 0; i < 2; i++)
        #pragma unroll
        for (int j = 0; j < 4; j++) wmma::fill_fragment(c[i][j], 0.f);

    for (int k0 = 0; k0 < IN_C; k0 += 32) {
        #pragma unroll
        for (int i = 0; i < 4; ++i) {
            int idx = tid * 4 + i;
            int r = idx >> 3, c4 = (idx & 7) * 4;
            int gm = bm + r;
            float4 v = make_float4(0.f, 0.f, 0.f, 0.f);
            if (gm < M) v = *(const float4*)&A[(size_t)gm * IN_C + k0 + c4];
            v.x = wmma::__float_to_tf32(v.x); v.y = wmma::__float_to_tf32(v.y);
            v.z = wmma::__float_to_tf32(v.z); v.w = wmma::__float_to_tf32(v.w);
            *(float4*)&As[r][c4] = v;
        }
        #pragma unroll
        for (int i = 0; i < 4; ++i) {
            int idx = tid * 4 + i;
            int kk = idx >> 5, n4 = (idx & 31) * 4;
            float4 v = *(const float4*)&W[(size_t)(k0 + kk) * HID_C + n4];
            v.x = wmma::__float_to_tf32(v.x); v.y = wmma::__float_to_tf32(v.y);
            v.z = wmma::__float_to_tf32(v.z); v.w = wmma::__float_to_tf32(v.w);
            *(float4*)&Bs[kk][n4] = v;
        }
        __syncthreads();
        #pragma unroll
        for (int ks = 0; ks < 32; ks += 8) {
            wmma::fragment<wmma::matrix_a, 16, 16, 8, wmma::precision::tf32, wmma::row_major> a[2];
            wmma::fragment<wmma::matrix_b, 16, 16, 8, wmma::precision::tf32, wmma::row_major> b[4];
            #pragma unroll
            for (int i = 0; i < 2; i++)
                wmma::load_matrix_sync(a[i], &As[wm * 32 + i * 16][ks], 40);
            #pragma unroll
            for (int j = 0; j < 4; j++)
                wmma::load_matrix_sync(b[j], &Bs[ks][wn * 64 + j * 16], 136);
            #pragma unroll
            for (int i = 0; i < 2; i++)
                #pragma unroll
                for (int j = 0; j < 4; j++)
                    wmma::mma_sync(c[i][j], a[i], b[j], c[i][j]);
        }
        __syncthreads();
    }
    #pragma unroll
    for (int i = 0; i < 2; i++)
        #pragma unroll
        for (int j = 0; j < 4; j++) {
            size_t off = (size_t)(bm + wm * 32 + i * 16) * HID_C + wn * 64 + j * 16;
            wmma::store_matrix_sync(&g_f1[off], c[i][j], HID_C, wmma::mem_row_major);
        }
}

// ---------------- gather layer 1 (warp per node) ----------------------------
__global__ __launch_bounds__(256) void gather1_kernel(int M) {
    int w    = (blockIdx.x * blockDim.x + threadIdx.x) >> 5;
    int lane = threadIdx.x & 31;
    if (w >= M) return;
    int start = g_row_start[w];
    int end   = g_row_start[w + 1];
    float dn = g_dinv[w];
    float4 acc = __ldg((const float4*)&g_f1[(size_t)w * HID_C] + lane);
    acc.x *= dn; acc.y *= dn; acc.z *= dn; acc.w *= dn;

    int i = start;
    for (; i + 4 <= end; i += 4) {
        int s0 = g_src[i], s1 = g_src[i + 1], s2 = g_src[i + 2], s3 = g_src[i + 3];
        float d0 = g_dinv[s0], d1 = g_dinv[s1], d2 = g_dinv[s2], d3 = g_dinv[s3];
        float4 v0 = __ldg((const float4*)&g_f1[(size_t)s0 * HID_C] + lane);
        float4 v1 = __ldg((const float4*)&g_f1[(size_t)s1 * HID_C] + lane);
        float4 v2 = __ldg((const float4*)&g_f1[(size_t)s2 * HID_C] + lane);
        float4 v3 = __ldg((const float4*)&g_f1[(size_t)s3 * HID_C] + lane);
        acc.x += v0.x * d0 + v1.x * d1 + v2.x * d2 + v3.x * d3;
        acc.y += v0.y * d0 + v1.y * d1 + v2.y * d2 + v3.y * d3;
        acc.z += v0.z * d0 + v1.z * d1 + v2.z * d2 + v3.z * d3;
        acc.w += v0.w * d0 + v1.w * d1 + v2.w * d2 + v3.w * d3;
    }
    for (; i < end; ++i) {
        int s = g_src[i];
        float ds = g_dinv[s];
        float4 v = __ldg((const float4*)&g_f1[(size_t)s * HID_C] + lane);
        acc.x += v.x * ds; acc.y += v.y * ds; acc.z += v.z * ds; acc.w += v.w * ds;
    }
    acc.x *= dn; acc.y *= dn; acc.z *= dn; acc.w *= dn;
    *((float4*)&g_a1[(size_t)w * HID_C] + lane) = acc;
}

// ---------------- GEMM2 (TF32 wmma): g_f2 = relu(a1 + b1) @ W2 (raw) --------
__global__ __launch_bounds__(256, 2) void gemm2_kernel(
    const float* __restrict__ W, const float* __restrict__ b1, int M) {
    __shared__ float As[128][40];
    __shared__ float Bs[32][72];
    __shared__ float b1s[HID_C];
    int tid = threadIdx.x;
    int wid = tid >> 5;
    int wm = wid & 3;
    int wn = wid >> 2;
    int bm = blockIdx.x * 128;
    if (tid < HID_C / 4) ((float4*)b1s)[tid] = ((const float4*)b1)[tid];
    __syncthreads();

    wmma::fragment<wmma::accumulator, 16, 16, 8, float> c[2][2];
    #pragma unroll
    for (int i = 0; i < 2; i++)
        #pragma unroll
        for (int j = 0; j < 2; j++) wmma::fill_fragment(c[i][j], 0.f);

    for (int k0 = 0; k0 < HID_C; k0 += 32) {
        #pragma unroll
        for (int i = 0; i < 4; ++i) {
            int idx = tid * 4 + i;
            int r = idx >> 3, c4 = (idx & 7) * 4;
            int gm = bm + r;
            float4 v = make_float4(0.f, 0.f, 0.f, 0.f);
            if (gm < M) {
                v = *(const float4*)&g_a1[(size_t)gm * HID_C + k0 + c4];
                v.x = fmaxf(v.x + b1s[k0 + c4 + 0], 0.f);
                v.y = fmaxf(v.y + b1s[k0 + c4 + 1], 0.f);
                v.z = fmaxf(v.z + b1s[k0 + c4 + 2], 0.f);
                v.w = fmaxf(v.w + b1s[k0 + c4 + 3], 0.f);
                v.x = wmma::__float_to_tf32(v.x); v.y = wmma::__float_to_tf32(v.y);
                v.z = wmma::__float_to_tf32(v.z); v.w = wmma::__float_to_tf32(v.w);
            }
            *(float4*)&As[r][c4] = v;
        }
        #pragma unroll
        for (int i = 0; i < 2; ++i) {
            int idx = tid * 2 + i;
            int kk = idx >> 4, n4 = (idx & 15) * 4;
            float4 v = *(const float4*)&W[(size_t)(k0 + kk) * OUT_C + n4];
            v.x = wmma::__float_to_tf32(v.x); v.y = wmma::__float_to_tf32(v.y);
            v.z = wmma::__float_to_tf32(v.z); v.w = wmma::__float_to_tf32(v.w);
            *(float4*)&Bs[kk][n4] = v;
        }
        __syncthreads();
        #pragma unroll
        for (int ks = 0; ks < 32; ks += 8) {
            wmma::fragment<wmma::matrix_a, 16, 16, 8, wmma::precision::tf32, wmma::row_major> a[2];
            wmma::fragment<wmma::matrix_b, 16, 16, 8, wmma::precision::tf32, wmma::row_major> b[2];
            #pragma unroll
            for (int i = 0; i < 2; i++)
                wmma::load_matrix_sync(a[i], &As[wm * 32 + i * 16][ks], 40);
            #pragma unroll
            for (int j = 0; j < 2; j++)
                wmma::load_matrix_sync(b[j], &Bs[ks][wn * 32 + j * 16], 72);
            #pragma unroll
            for (int i = 0; i < 2; i++)
                #pragma unroll
                for (int j = 0; j < 2; j++)
                    wmma::mma_sync(c[i][j], a[i], b[j], c[i][j]);
        }
        __syncthreads();
    }
    #pragma unroll
    for (int i = 0; i < 2; i++)
        #pragma unroll
        for (int j = 0; j < 2; j++) {
            size_t off = (size_t)(bm + wm * 32 + i * 16) * OUT_C + wn * 32 + j * 16;
            wmma::store_matrix_sync(&g_f2[off], c[i][j], OUT_C, wmma::mem_row_major);
        }
}

// ---------------- gather layer 2 + bias (16 lanes per node) -----------------
__global__ __launch_bounds__(256) void gather2_kernel(
    float* __restrict__ out, const float* __restrict__ b2, int M) {
    int t    = blockIdx.x * blockDim.x + threadIdx.x;
    int n    = t >> 4;
    int lane = t & 15;
    if (n >= M) return;
    int start = g_row_start[n];
    int end   = g_row_start[n + 1];
    float dn = g_dinv[n];
    float4 acc = __ldg((const float4*)&g_f2[(size_t)n * OUT_C] + lane);
    acc.x *= dn; acc.y *= dn; acc.z *= dn; acc.w *= dn;

    int i = start;
    for (; i + 4 <= end; i += 4) {
        int s0 = g_src[i], s1 = g_src[i + 1], s2 = g_src[i + 2], s3 = g_src[i + 3];
        float d0 = g_dinv[s0], d1 = g_dinv[s1], d2 = g_dinv[s2], d3 = g_dinv[s3];
        float4 v0 = __ldg((const float4*)&g_f2[(size_t)s0 * OUT_C] + lane);
        float4 v1 = __ldg((const float4*)&g_f2[(size_t)s1 * OUT_C] + lane);
        float4 v2 = __ldg((const float4*)&g_f2[(size_t)s2 * OUT_C] + lane);
        float4 v3 = __ldg((const float4*)&g_f2[(size_t)s3 * OUT_C] + lane);
        acc.x += v0.x * d0 + v1.x * d1 + v2.x * d2 + v3.x * d3;
        acc.y += v0.y * d0 + v1.y * d1 + v2.y * d2 + v3.y * d3;
        acc.z += v0.z * d0 + v1.z * d1 + v2.z * d2 + v3.z * d3;
        acc.w += v0.w * d0 + v1.w * d1 + v2.w * d2 + v3.w * d3;
    }
    for (; i < end; ++i) {
        int s = g_src[i];
        float ds = g_dinv[s];
        float4 v = __ldg((const float4*)&g_f2[(size_t)s * OUT_C] + lane);
        acc.x += v.x * ds; acc.y += v.y * ds; acc.z += v.z * ds; acc.w += v.w * ds;
    }
    float4 bb = __ldg((const float4*)b2 + lane);
    acc.x = acc.x * dn + bb.x; acc.y = acc.y * dn + bb.y;
    acc.z = acc.z * dn + bb.z; acc.w = acc.w * dn + bb.w;
    *((float4*)&out[(size_t)n * OUT_C] + lane) = acc;
}

// ---------------- launch ----------------------------------------------------
extern "C" void kernel_launch(void* const* d_in, const int* in_sizes, int n_in,
                              void* d_out, int out_size) {
    const float* features = (const float*)d_in[0];
    const void*  edge_idx = d_in[1];
    const float* W1 = (const float*)d_in[2];
    const float* b1 = (const float*)d_in[3];
    const float* W2 = (const float*)d_in[4];
    const float* b2 = (const float*)d_in[5];
    float* out = (float*)d_out;

    int M = in_sizes[0] / IN_C;       // 50000
    int E = in_sizes[1] / 2;          // 800000

    prep_kernel<<<(M + 255) / 256, 256>>>((const long long*)edge_idx, E, M);
    count_deg_kernel<<<(E + 255) / 256, 256>>>(edge_idx, E);
    scan1_kernel<<<SCAN_B, 256>>>(M);
    scan2_kernel<<<1, 256>>>();
    scan3_kernel<<<SCAN_B, 256>>>(M, E);
    fill_kernel<<<(E + 255) / 256, 256>>>(edge_idx, E);

    int gblocks = (M + 127) / 128;    // 391
    gemm1_kernel<<<gblocks, 256>>>(features, W1, M);

    long long t1 = (long long)M * 32;
    gather1_kernel<<<(unsigned)((t1 + 255) / 256), 256>>>(M);

    gemm2_kernel<<<gblocks, 256>>>(W2, b1, M);

    long long t2 = (long long)M * 16;
    gather2_kernel<<<(unsigned)((t2 + 255) / 256), 256>>>(out, b2, M);
}